// round 1
// baseline (speedup 1.0000x reference)
#include <cuda_runtime.h>
#include <math.h>

// ---------------- problem constants ----------------
#define BATCH   2
#define NTOK    5760
#define M_TOT   (BATCH * NTOK)   // 11520 tokens
#define DD      512              // model dim
#define HDIM    1960             // hidden dim
#define KTAPS   49               // 7x7
#define KH      7
#define CCH     40               // fold channels = 1960/49
#define HH      60
#define WWID    108
#define PAD     3
#define HP      66               // H + 2*PAD
#define WP      114              // W + 2*PAD
#define OHN     20               // (60+6-7)/3+1
#define OWN     36               // (108+6-7)/3+1
#define LLP     720              // OHN*OWN
#define BPF     16               // (b*n)/L
#define IMGPIX  (HP * WP)        // 7524
#define NIMG    (BPF * CCH)      // 640

// ---------------- scratch (static device globals; no allocations) ----------------
__device__ float g_h[(size_t)M_TOT * HDIM];           // 90.3 MB : x@W1+b1
__device__ float g_img[(size_t)NIMG * IMGPIX];        // 19.3 MB : folded+normalized padded images
__device__ float g_g[(size_t)M_TOT * HDIM];           // 90.3 MB : gelu(unfold(img))

// ---------------- generic fp32 SGEMM: C = A*B + bias ----------------
// Assumes: M % 128 == 0, K % 8 == 0, N % 4 == 0 (true for both GEMMs here).
// Block tile 128x128, BK=8, 256 threads, 8x8 per thread.
__global__ __launch_bounds__(256) void sgemm_bias(
    const float* __restrict__ A, const float* __restrict__ B,
    const float* __restrict__ bias, float* __restrict__ C,
    int M, int N, int K)
{
    const int BM = 128, BN = 128, BK = 8, TM = 8, TN = 8;
    __shared__ float As[BK][BM];
    __shared__ float Bs[BK][BN];

    const int tid  = threadIdx.x;
    const int row0 = blockIdx.y * BM;
    const int col0 = blockIdx.x * BN;

    // A-tile load map: thread -> (arow in [0,128), acol in {0,4}) as one float4
    const int arow = tid >> 1;
    const int acol = (tid & 1) << 2;
    // B-tile load map: thread -> (brow in [0,8), bcol in [0,128) step 4) as one float4
    const int brow = tid >> 5;
    const int bcol = (tid & 31) << 2;

    const int trow = (tid >> 4) * TM;   // 16x16 thread grid over the 128x128 tile
    const int tcol = (tid & 15) * TN;

    float acc[TM][TN];
#pragma unroll
    for (int i = 0; i < TM; i++)
#pragma unroll
        for (int j = 0; j < TN; j++) acc[i][j] = 0.f;

    const float* Aptr = A + (size_t)(row0 + arow) * K + acol;
    const int gcol = col0 + bcol;

    for (int k0 = 0; k0 < K; k0 += BK) {
        // load A (always in-bounds: M%128==0, K%8==0)
        float4 av = *reinterpret_cast<const float4*>(Aptr + k0);
        As[acol + 0][arow] = av.x;
        As[acol + 1][arow] = av.y;
        As[acol + 2][arow] = av.z;
        As[acol + 3][arow] = av.w;
        // load B (N-guard: gcol%4==0 && N%4==0 -> float4 fully in or out)
        float4 bv = make_float4(0.f, 0.f, 0.f, 0.f);
        if (gcol < N)
            bv = *reinterpret_cast<const float4*>(&B[(size_t)(k0 + brow) * N + gcol]);
        Bs[brow][bcol + 0] = bv.x;
        Bs[brow][bcol + 1] = bv.y;
        Bs[brow][bcol + 2] = bv.z;
        Bs[brow][bcol + 3] = bv.w;
        __syncthreads();

#pragma unroll
        for (int kk = 0; kk < BK; kk++) {
            float ar[TM], br[TN];
            // vectorized shared reads (trow, tcol are multiples of 8 -> 16B aligned)
            *reinterpret_cast<float4*>(&ar[0]) = *reinterpret_cast<const float4*>(&As[kk][trow]);
            *reinterpret_cast<float4*>(&ar[4]) = *reinterpret_cast<const float4*>(&As[kk][trow + 4]);
            *reinterpret_cast<float4*>(&br[0]) = *reinterpret_cast<const float4*>(&Bs[kk][tcol]);
            *reinterpret_cast<float4*>(&br[4]) = *reinterpret_cast<const float4*>(&Bs[kk][tcol + 4]);
#pragma unroll
            for (int i = 0; i < TM; i++)
#pragma unroll
                for (int j = 0; j < TN; j++)
                    acc[i][j] = fmaf(ar[i], br[j], acc[i][j]);
        }
        __syncthreads();
    }

    // epilogue: += bias, store (N-guard in float4 chunks)
#pragma unroll
    for (int i = 0; i < TM; i++) {
        const size_t row = (size_t)(row0 + trow + i);
#pragma unroll
        for (int j = 0; j < TN; j += 4) {
            const int col = col0 + tcol + j;
            if (col < N) {
                float4 v;
                v.x = acc[i][j + 0] + bias[col + 0];
                v.y = acc[i][j + 1] + bias[col + 1];
                v.z = acc[i][j + 2] + bias[col + 2];
                v.w = acc[i][j + 3] + bias[col + 3];
                *reinterpret_cast<float4*>(&C[row * (size_t)N + col]) = v;
            }
        }
    }
}

// ---------------- fold (gather form) + overlap-count normalize + crop/zero-pad ----------------
// img[bp, c, pi, pj] = (1/count) * sum over contributing (l, k) of h[bp*720+l, c*49+k]
// Zero outside the crop region [PAD, PAD+H) x [PAD, PAD+W) (matches fold-crop + zero re-pad).
__global__ void fold_kernel(const float* __restrict__ h, float* __restrict__ img)
{
    const int idx = blockIdx.x * blockDim.x + threadIdx.x;
    if (idx >= NIMG * IMGPIX) return;
    const int pix = idx % IMGPIX;
    const int bc  = idx / IMGPIX;
    const int c   = bc % CCH;
    const int bp  = bc / CCH;
    const int pi  = pix / WP;
    const int pj  = pix % WP;

    float out = 0.f;
    if (pi >= PAD && pi < PAD + HH && pj >= PAD && pj < PAD + WWID) {
        // contributing output-patch rows: ceil((pi-6)/3) <= oi <= floor(pi/3), clamped to [0, OHN)
        const int oi_lo = max(0, (pi - 4) / 3);     // == max(0, ceil((pi-6)/3)) for pi >= 3
        const int oi_hi = min(OHN - 1, pi / 3);
        const int oj_lo = max(0, (pj - 4) / 3);
        const int oj_hi = min(OWN - 1, pj / 3);

        float sum = 0.f;
        for (int oi = oi_lo; oi <= oi_hi; ++oi) {
            const int ki = pi - 3 * oi;
            for (int oj = oj_lo; oj <= oj_hi; ++oj) {
                const int kj = pj - 3 * oj;
                const int l = oi * OWN + oj;
                const int k = ki * KH + kj;
                sum += h[(size_t)(bp * LLP + l) * HDIM + c * KTAPS + k];
            }
        }
        const int cnt = (oi_hi - oi_lo + 1) * (oj_hi - oj_lo + 1);
        out = sum / (float)cnt;
    }
    img[idx] = out;
}

// ---------------- unfold + exact GELU ----------------
// g[token, c*49+k] = gelu( img[bp*40+c, (oi*3+ki)*WP + (oj*3+kj)] )
__global__ void unfold_gelu_kernel(const float* __restrict__ img, float* __restrict__ g)
{
    const int idx = blockIdx.x * blockDim.x + threadIdx.x;   // < 22,579,200 (fits int32)
    if (idx >= M_TOT * HDIM) return;
    const int j     = idx % HDIM;
    const int token = idx / HDIM;
    const int bp = token / LLP;
    const int l  = token % LLP;
    const int c  = j / KTAPS;
    const int k  = j % KTAPS;
    const int oi = l / OWN, oj = l % OWN;
    const int ki = k / KH,  kj = k % KH;
    const int pix = (oi * 3 + ki) * WP + (oj * 3 + kj);

    const float v = img[(size_t)(bp * CCH + c) * IMGPIX + pix];
    // exact GELU: 0.5*x*(1+erf(x/sqrt(2)))
    g[idx] = 0.5f * v * (1.f + erff(v * 0.7071067811865475f));
}

// ---------------- launch ----------------
extern "C" void kernel_launch(void* const* d_in, const int* in_sizes, int n_in,
                              void* d_out, int out_size)
{
    const float* x  = (const float*)d_in[0];   // (2, 5760, 512)
    const float* W1 = (const float*)d_in[1];   // (512, 1960)
    const float* b1 = (const float*)d_in[2];   // (1960,)
    const float* W2 = (const float*)d_in[3];   // (1960, 512)
    const float* b2 = (const float*)d_in[4];   // (512,)
    float* out = (float*)d_out;                // (2, 5760, 512)

    float *h_ptr, *img_ptr, *g_ptr;
    cudaGetSymbolAddress((void**)&h_ptr,   g_h);
    cudaGetSymbolAddress((void**)&img_ptr, g_img);
    cudaGetSymbolAddress((void**)&g_ptr,   g_g);

    // GEMM1: h = x @ W1 + b1   (11520 x 1960, K = 512)
    {
        dim3 grid((HDIM + 127) / 128, M_TOT / 128);   // (16, 90)
        sgemm_bias<<<grid, 256>>>(x, W1, b1, h_ptr, M_TOT, HDIM, DD);
    }
    // fold + normalize
    {
        const int total = NIMG * IMGPIX;              // 4,815,360
        fold_kernel<<<(total + 255) / 256, 256>>>(h_ptr, img_ptr);
    }
    // unfold + gelu
    {
        const int total = M_TOT * HDIM;               // 22,579,200
        unfold_gelu_kernel<<<(total + 255) / 256, 256>>>(img_ptr, g_ptr);
    }
    // GEMM2: out = g @ W2 + b2  (11520 x 512, K = 1960)
    {
        dim3 grid((DD + 127) / 128, M_TOT / 128);     // (4, 90)
        sgemm_bias<<<grid, 256>>>(g_ptr, W2, b2, out, M_TOT, DD, HDIM);
    }
}